// round 15
// baseline (speedup 1.0000x reference)
#include <cuda_runtime.h>
#include <cuda_fp16.h>
#include <cstdint>

// ============================================================================
// Fused LSTM cell via plain fp16 mma.sync GEMM (plain sm_103 PTX).
//   g[b, n] = sum_k Z[b,k] * Vt[n,k],  Z = [x | h_old] (K=768),
//   n = (h<<2)|g interleaved gate-columns (2048 total).
//   Single product: Z and V rounded to fp16, fp32 accumulate (rel err ~3e-4).
// R15: merged prep kernel; fill_stage moved before compute (earlier cp.async
//      issue); c_old prefetched into SMEM during prologue (epilogue DRAM
//      latency hidden). Core: warp tile 32x64, 3-stage single-barrier
//      pipeline, 2 CTAs/SM.
// ============================================================================

#define BM 128
#define BN 128
#define BK 64
#define NIT 12              // 768 / 64
#define NTHR 256
#define N_STAGE 3

#define SA   0
#define SB   16384
#define STAGE_BYTES 32768   // 32 KB: A 16K + B 16K
#define SM_COLD (N_STAGE * STAGE_BYTES)        // 96 KB: c_old tile (16 KB)
#define SM_TOTAL (SM_COLD + 16384)             // 112 KB -> 2 CTAs/SM (224+2 KB)
#define EPI_LD 132                             // padded f32 row stride, epi < 68 KB

__device__ __align__(16) __half g_V[2048 * 768];
__device__ __align__(16) __half g_Z[65536 * 768];

// ---------------------------------------------------------------------------
__device__ __forceinline__ uint32_t smem_u32(const void* p) {
    uint32_t a;
    asm("{ .reg .u64 t; cvta.to.shared.u64 t, %1; cvt.u32.u64 %0, t; }" : "=r"(a) : "l"(p));
    return a;
}
__device__ __forceinline__ uint32_t swz(uint32_t off) { return off ^ ((off >> 3) & 0x70); }

__device__ __forceinline__ void cp16(uint32_t dst, const void* src) {
    asm volatile("cp.async.cg.shared.global [%0], [%1], 16;" :: "r"(dst), "l"(src) : "memory");
}
#define CP_COMMIT() asm volatile("cp.async.commit_group;" ::: "memory")
template <int N> __device__ __forceinline__ void cp_wait() {
    asm volatile("cp.async.wait_group %0;" :: "n"(N) : "memory");
}

__device__ __forceinline__ void ldm4(uint32_t r[4], uint32_t a) {
    asm volatile("ldmatrix.sync.aligned.m8n8.x4.shared.b16 {%0,%1,%2,%3}, [%4];"
        : "=r"(r[0]), "=r"(r[1]), "=r"(r[2]), "=r"(r[3]) : "r"(a));
}
__device__ __forceinline__ void mma16816(float d[4], const uint32_t a[4],
                                         uint32_t b0, uint32_t b1) {
    asm volatile(
        "mma.sync.aligned.m16n8k16.row.col.f32.f16.f16.f32 "
        "{%0,%1,%2,%3}, {%4,%5,%6,%7}, {%8,%9}, {%0,%1,%2,%3};"
        : "+f"(d[0]), "+f"(d[1]), "+f"(d[2]), "+f"(d[3])
        : "r"(a[0]), "r"(a[1]), "r"(a[2]), "r"(a[3]), "r"(b0), "r"(b1));
}

__device__ __forceinline__ float sigmoidf_(float x) {
    return 1.0f / (1.0f + __expf(-x));
}
__device__ __forceinline__ float tanhf_(float x) {
    return 2.0f / (1.0f + __expf(-2.0f * x)) - 1.0f;
}

// ---------------------------------------------------------------------------
// Merged prep: fp16 round Z = [x | h_old] (float4 granularity) AND
// transpose+round weights Vt[n][k], n = (h<<2)|g.
// ---------------------------------------------------------------------------
#define ZTASKS (65536 * 192)            // B * 192 float4 tasks
#define WTASKS (2048 * 768)

__global__ void lstm_prep(const float* __restrict__ x, const float* __restrict__ h_old,
                          const float* __restrict__ U, const float* __restrict__ W,
                          int B)
{
    int idx = blockIdx.x * blockDim.x + threadIdx.x;
    int zN = B * 192;
    if (idx < zN) {
        int m = idx / 192;
        int k = (idx - m * 192) * 4;
        float4 v = (k < 256)
            ? *reinterpret_cast<const float4*>(x + (size_t)m * 256 + k)
            : *reinterpret_cast<const float4*>(h_old + (size_t)m * 512 + (k - 256));
        __half2 h01 = __float22half2_rn(make_float2(v.x, v.y));
        __half2 h23 = __float22half2_rn(make_float2(v.z, v.w));
        uint2 hp;
        hp.x = *reinterpret_cast<uint32_t*>(&h01);
        hp.y = *reinterpret_cast<uint32_t*>(&h23);
        *reinterpret_cast<uint2*>(g_Z + (size_t)m * 768 + k) = hp;
    } else {
        int wi = idx - zN;
        if (wi >= WTASKS) return;
        int n = wi / 768, kk = wi - n * 768;
        int g = n & 3, h = n >> 2;
        float v = (kk < 256) ? U[((size_t)g * 256 + kk) * 512 + h]
                             : W[((size_t)g * 512 + (kk - 256)) * 512 + h];
        g_V[wi] = __float2half_rn(v);
    }
}

// ---------------------------------------------------------------------------
// Stage fill: 8 cp.async x 16B per thread.
//   A: 128 rows x 128B;  B: 128 rows x 128B.
// ---------------------------------------------------------------------------
__device__ __forceinline__ void fill_stage(uint32_t sst, int it, int tid, int m0, int n0g) {
    const int kt2 = it * 128;   // byte offset within 1536-byte k-row
    const int row = tid >> 1;
    const int kh  = (tid & 1) * 64;
    // ---- A ----
    {
        const char* src = (const char*)g_Z + (size_t)(m0 + row) * 1536 + kt2 + kh;
        #pragma unroll
        for (int c = 0; c < 4; c++)
            cp16(sst + SA + swz((uint32_t)(row * 128 + kh + c * 16)), src + c * 16);
    }
    // ---- B ----
    {
        const char* src = (const char*)g_V + (size_t)(n0g + row) * 1536 + kt2 + kh;
        #pragma unroll
        for (int c = 0; c < 4; c++)
            cp16(sst + SB + swz((uint32_t)(row * 128 + kh + c * 16)), src + c * 16);
    }
}

// ---------------------------------------------------------------------------
// Main GEMM + epilogue. 8 warps (4m x 2n), warp tile 32x64.
// 3-stage pipeline, one __syncthreads per k-iteration, 2 CTAs/SM.
// c_old prefetched to SMEM in prologue.
// ---------------------------------------------------------------------------
__global__ __launch_bounds__(NTHR, 2)
void lstm_mma_kernel(const float* __restrict__ c_old,
                     const float* __restrict__ bU,
                     const float* __restrict__ bW,
                     float* __restrict__ out,
                     int B)
{
    extern __shared__ char sm[];
    const uint32_t sb = smem_u32(sm);
    const int tid  = threadIdx.x;
    const int wid  = tid >> 5;
    const int lane = tid & 31;

    const int m0  = blockIdx.y * BM;
    const int n0g = blockIdx.x * BN;
    const int h0  = blockIdx.x * 32;

    const int wm = (wid >> 1) * 32;   // warp m offset (4 tiles -> 128)
    const int wn = (wid & 1) * 64;    // warp n offset (2 tiles -> 128)

    const int a_row = lane & 15;
    const int a_kh  = (lane >> 4) * 16;
    const int b_row = (lane & 7) + ((lane & 16) >> 1);
    const int b_kh  = ((lane >> 3) & 1) * 16;

    float acc[2][8][4];
    #pragma unroll
    for (int mt = 0; mt < 2; mt++)
        #pragma unroll
        for (int nt = 0; nt < 8; nt++)
            #pragma unroll
            for (int r = 0; r < 4; r++) acc[mt][nt][r] = 0.0f;

    // ---- prologue: c_old prefetch + 2 stages in flight ----
    {
        // 128 rows x 32 f32 (128B/row) = 1024 x 16B chunks, 4 per thread
        #pragma unroll
        for (int c = 0; c < 4; c++) {
            int idx = c * NTHR + tid;
            int m = idx >> 3;
            int col4 = (idx & 7) * 4;
            cp16(sb + SM_COLD + (uint32_t)idx * 16,
                 c_old + (size_t)(m0 + m) * 512 + h0 + col4);
        }
        CP_COMMIT();
    }
    fill_stage(sb + 0 * STAGE_BYTES, 0, tid, m0, n0g); CP_COMMIT();
    fill_stage(sb + 1 * STAGE_BYTES, 1, tid, m0, n0g); CP_COMMIT();

    #pragma unroll 1
    for (int it = 0; it < NIT; it++) {
        if (it + 1 < NIT) cp_wait<1>(); else cp_wait<0>();
        __syncthreads();   // stage it%3 visible to all threads

        // refill stage (it+2)%3 == (it-1)%3 FIRST — its readers were fenced by
        // the barrier above; issuing before compute gives the loads ~2 iters
        // of latency slack.
        if (it + 2 < NIT) {
            fill_stage(sb + (uint32_t)((it + 2) % 3) * STAGE_BYTES, it + 2, tid, m0, n0g);
            CP_COMMIT();
        }

        const uint32_t st = sb + (uint32_t)(it % 3) * STAGE_BYTES;

        #pragma unroll
        for (int ks = 0; ks < 4; ks++) {
            const uint32_t kb = ks * 32;
            uint32_t aa[2][4], bb[4][4];

            #pragma unroll
            for (int mt = 0; mt < 2; mt++)
                ldm4(aa[mt], st + SA + swz((uint32_t)((wm + mt * 16 + a_row) * 128 + kb + a_kh)));
            #pragma unroll
            for (int p = 0; p < 4; p++)
                ldm4(bb[p], st + SB + swz((uint32_t)((wn + p * 16 + b_row) * 128 + kb + b_kh)));

            #pragma unroll
            for (int mt = 0; mt < 2; mt++)
                #pragma unroll
                for (int nt = 0; nt < 8; nt++)
                    mma16816(acc[mt][nt], aa[mt], bb[nt >> 1][(nt & 1) * 2], bb[nt >> 1][(nt & 1) * 2 + 1]);
        }
    }

    __syncthreads();   // all compute done before smem reuse

    // ---- epilogue: accums -> SMEM (row stride 132 f32) ----
    float* epi = reinterpret_cast<float*>(sm);
    #pragma unroll
    for (int mt = 0; mt < 2; mt++) {
        #pragma unroll
        for (int nt = 0; nt < 8; nt++) {
            const int m = wm + mt * 16 + (lane >> 2);
            const int n = wn + nt * 8 + (lane & 3) * 2;
            *reinterpret_cast<float2*>(&epi[m * EPI_LD + n]) =
                make_float2(acc[mt][nt][0], acc[mt][nt][1]);
            *reinterpret_cast<float2*>(&epi[(m + 8) * EPI_LD + n]) =
                make_float2(acc[mt][nt][2], acc[mt][nt][3]);
        }
    }
    __syncthreads();

    // ---- gates + state update (c_old from SMEM) ----
    {
        const int h_loc = tid & 31;       // 32 h per CTA
        const int mrow0 = tid >> 5;       // 8 row groups
        const size_t BH = (size_t)B * 512;
        const float* cold = reinterpret_cast<const float*>(sm + SM_COLD);
        const float bi = bU[0 * 512 + h0 + h_loc] + bW[0 * 512 + h0 + h_loc];
        const float bf = bU[1 * 512 + h0 + h_loc] + bW[1 * 512 + h0 + h_loc];
        const float bo = bU[2 * 512 + h0 + h_loc] + bW[2 * 512 + h0 + h_loc];
        const float bc = bU[3 * 512 + h0 + h_loc] + bW[3 * 512 + h0 + h_loc];

        #pragma unroll
        for (int j = 0; j < 16; j++) {
            const int m = mrow0 + 8 * j;
            float4 gv = *reinterpret_cast<const float4*>(&epi[m * EPI_LD + h_loc * 4]);
            const float i_t = sigmoidf_(gv.x + bi);
            const float f_t = sigmoidf_(gv.y + bf);
            const float o_t = sigmoidf_(gv.z + bo);
            const float c_t = tanhf_(gv.w + bc);
            const size_t off = (size_t)(m0 + m) * 512 + h0 + h_loc;
            const float cn = i_t * c_t + f_t * cold[m * 32 + h_loc];
            out[off]      = o_t * tanhf_(cn);   // h_new
            out[BH + off] = cn;                 // c_new
        }
    }
}

// ---------------------------------------------------------------------------
extern "C" void kernel_launch(void* const* d_in, const int* in_sizes, int n_in,
                              void* d_out, int out_size)
{
    const float* x     = (const float*)d_in[0];  // [B, 256]
    const float* h_old = (const float*)d_in[1];  // [B, 512]
    const float* c_old = (const float*)d_in[2];  // [B, 512]
    const float* U     = (const float*)d_in[3];  // [4, 256, 512]
    const float* bU    = (const float*)d_in[4];  // [4, 512]
    const float* W     = (const float*)d_in[5];  // [4, 512, 512]
    const float* bW    = (const float*)d_in[6];  // [4, 512]
    float* out = (float*)d_out;                  // [2, B, 512]

    int B = in_sizes[0] / 256;

    cudaFuncSetAttribute(lstm_mma_kernel,
                         cudaFuncAttributeMaxDynamicSharedMemorySize, SM_TOTAL);

    int ptasks = B * 192 + WTASKS;
    lstm_prep<<<(ptasks + 255) / 256, 256>>>(x, h_old, U, W, B);

    dim3 grid(2048 / BN, B / BM);   // (16, 512) — n fastest for L2 A-stripe reuse
    lstm_mma_kernel<<<grid, NTHR, SM_TOTAL>>>(c_old, bU, bW, out, B);
}

// round 16
// speedup vs baseline: 1.1138x; 1.1138x over previous
#include <cuda_runtime.h>
#include <cuda_fp16.h>
#include <cstdint>

// ============================================================================
// Fused LSTM cell via plain fp16 mma.sync GEMM (plain sm_103 PTX).
//   g[b, n] = sum_k Z[b,k] * Vt[n,k],  Z = [x | h_old] (K=768),
//   n = (h<<2)|g interleaved gate-columns (2048 total).
//   Single product: Z and V rounded to fp16, fp32 accumulate (rel err ~3e-4).
// R16: merged prep (kept); fill_stage back at end-of-compute (R15 LSU-burst
//      regression reverted); c_old prefetched into REGISTERS across the
//      epilogue barrier. Core: warp tile 32x64, 3-stage single-barrier
//      pipeline, 2 CTAs/SM, 96 KB smem/CTA.
// ============================================================================

#define BM 128
#define BN 128
#define BK 64
#define NIT 12              // 768 / 64
#define NTHR 256
#define N_STAGE 3

#define SA   0
#define SB   16384
#define STAGE_BYTES 32768   // 32 KB: A 16K + B 16K
#define SM_TOTAL (N_STAGE * STAGE_BYTES)   // 96 KB -> 2 CTAs/SM (192 KB)
#define EPI_LD 132                         // padded f32 row stride for epilogue

__device__ __align__(16) __half g_V[2048 * 768];
__device__ __align__(16) __half g_Z[65536 * 768];

// ---------------------------------------------------------------------------
__device__ __forceinline__ uint32_t smem_u32(const void* p) {
    uint32_t a;
    asm("{ .reg .u64 t; cvta.to.shared.u64 t, %1; cvt.u32.u64 %0, t; }" : "=r"(a) : "l"(p));
    return a;
}
__device__ __forceinline__ uint32_t swz(uint32_t off) { return off ^ ((off >> 3) & 0x70); }

__device__ __forceinline__ void cp16(uint32_t dst, const void* src) {
    asm volatile("cp.async.cg.shared.global [%0], [%1], 16;" :: "r"(dst), "l"(src) : "memory");
}
#define CP_COMMIT() asm volatile("cp.async.commit_group;" ::: "memory")
template <int N> __device__ __forceinline__ void cp_wait() {
    asm volatile("cp.async.wait_group %0;" :: "n"(N) : "memory");
}

__device__ __forceinline__ void ldm4(uint32_t r[4], uint32_t a) {
    asm volatile("ldmatrix.sync.aligned.m8n8.x4.shared.b16 {%0,%1,%2,%3}, [%4];"
        : "=r"(r[0]), "=r"(r[1]), "=r"(r[2]), "=r"(r[3]) : "r"(a));
}
__device__ __forceinline__ void mma16816(float d[4], const uint32_t a[4],
                                         uint32_t b0, uint32_t b1) {
    asm volatile(
        "mma.sync.aligned.m16n8k16.row.col.f32.f16.f16.f32 "
        "{%0,%1,%2,%3}, {%4,%5,%6,%7}, {%8,%9}, {%0,%1,%2,%3};"
        : "+f"(d[0]), "+f"(d[1]), "+f"(d[2]), "+f"(d[3])
        : "r"(a[0]), "r"(a[1]), "r"(a[2]), "r"(a[3]), "r"(b0), "r"(b1));
}

__device__ __forceinline__ float sigmoidf_(float x) {
    return 1.0f / (1.0f + __expf(-x));
}
__device__ __forceinline__ float tanhf_(float x) {
    return 2.0f / (1.0f + __expf(-2.0f * x)) - 1.0f;
}

// ---------------------------------------------------------------------------
// Merged prep: fp16 round Z = [x | h_old] (float4 granularity) AND
// transpose+round weights Vt[n][k], n = (h<<2)|g.
// ---------------------------------------------------------------------------
#define WTASKS (2048 * 768)

__global__ void lstm_prep(const float* __restrict__ x, const float* __restrict__ h_old,
                          const float* __restrict__ U, const float* __restrict__ W,
                          int B)
{
    int idx = blockIdx.x * blockDim.x + threadIdx.x;
    int zN = B * 192;
    if (idx < zN) {
        int m = idx / 192;
        int k = (idx - m * 192) * 4;
        float4 v = (k < 256)
            ? *reinterpret_cast<const float4*>(x + (size_t)m * 256 + k)
            : *reinterpret_cast<const float4*>(h_old + (size_t)m * 512 + (k - 256));
        __half2 h01 = __float22half2_rn(make_float2(v.x, v.y));
        __half2 h23 = __float22half2_rn(make_float2(v.z, v.w));
        uint2 hp;
        hp.x = *reinterpret_cast<uint32_t*>(&h01);
        hp.y = *reinterpret_cast<uint32_t*>(&h23);
        *reinterpret_cast<uint2*>(g_Z + (size_t)m * 768 + k) = hp;
    } else {
        int wi = idx - zN;
        if (wi >= WTASKS) return;
        int n = wi / 768, kk = wi - n * 768;
        int g = n & 3, h = n >> 2;
        float v = (kk < 256) ? U[((size_t)g * 256 + kk) * 512 + h]
                             : W[((size_t)g * 512 + (kk - 256)) * 512 + h];
        g_V[wi] = __float2half_rn(v);
    }
}

// ---------------------------------------------------------------------------
// Stage fill: 8 cp.async x 16B per thread.
//   A: 128 rows x 128B;  B: 128 rows x 128B.
// ---------------------------------------------------------------------------
__device__ __forceinline__ void fill_stage(uint32_t sst, int it, int tid, int m0, int n0g) {
    const int kt2 = it * 128;   // byte offset within 1536-byte k-row
    const int row = tid >> 1;
    const int kh  = (tid & 1) * 64;
    // ---- A ----
    {
        const char* src = (const char*)g_Z + (size_t)(m0 + row) * 1536 + kt2 + kh;
        #pragma unroll
        for (int c = 0; c < 4; c++)
            cp16(sst + SA + swz((uint32_t)(row * 128 + kh + c * 16)), src + c * 16);
    }
    // ---- B ----
    {
        const char* src = (const char*)g_V + (size_t)(n0g + row) * 1536 + kt2 + kh;
        #pragma unroll
        for (int c = 0; c < 4; c++)
            cp16(sst + SB + swz((uint32_t)(row * 128 + kh + c * 16)), src + c * 16);
    }
}

// ---------------------------------------------------------------------------
// Main GEMM + epilogue. 8 warps (4m x 2n), warp tile 32x64.
// 3-stage pipeline, one __syncthreads per k-iteration, 2 CTAs/SM.
// ---------------------------------------------------------------------------
__global__ __launch_bounds__(NTHR, 2)
void lstm_mma_kernel(const float* __restrict__ c_old,
                     const float* __restrict__ bU,
                     const float* __restrict__ bW,
                     float* __restrict__ out,
                     int B)
{
    extern __shared__ char sm[];
    const uint32_t sb = smem_u32(sm);
    const int tid  = threadIdx.x;
    const int wid  = tid >> 5;
    const int lane = tid & 31;

    const int m0  = blockIdx.y * BM;
    const int n0g = blockIdx.x * BN;
    const int h0  = blockIdx.x * 32;

    const int wm = (wid >> 1) * 32;   // warp m offset (4 tiles -> 128)
    const int wn = (wid & 1) * 64;    // warp n offset (2 tiles -> 128)

    const int a_row = lane & 15;
    const int a_kh  = (lane >> 4) * 16;
    const int b_row = (lane & 7) + ((lane & 16) >> 1);
    const int b_kh  = ((lane >> 3) & 1) * 16;

    float acc[2][8][4];
    #pragma unroll
    for (int mt = 0; mt < 2; mt++)
        #pragma unroll
        for (int nt = 0; nt < 8; nt++)
            #pragma unroll
            for (int r = 0; r < 4; r++) acc[mt][nt][r] = 0.0f;

    // ---- pipeline prologue: 2 stages in flight ----
    fill_stage(sb + 0 * STAGE_BYTES, 0, tid, m0, n0g); CP_COMMIT();
    fill_stage(sb + 1 * STAGE_BYTES, 1, tid, m0, n0g); CP_COMMIT();

    #pragma unroll 1
    for (int it = 0; it < NIT; it++) {
        if (it + 1 < NIT) cp_wait<1>(); else cp_wait<0>();
        __syncthreads();   // stage it%3 visible to all threads

        const uint32_t st = sb + (uint32_t)(it % 3) * STAGE_BYTES;

        #pragma unroll
        for (int ks = 0; ks < 4; ks++) {
            const uint32_t kb = ks * 32;
            uint32_t aa[2][4], bb[4][4];

            #pragma unroll
            for (int mt = 0; mt < 2; mt++)
                ldm4(aa[mt], st + SA + swz((uint32_t)((wm + mt * 16 + a_row) * 128 + kb + a_kh)));
            #pragma unroll
            for (int p = 0; p < 4; p++)
                ldm4(bb[p], st + SB + swz((uint32_t)((wn + p * 16 + b_row) * 128 + kb + b_kh)));

            #pragma unroll
            for (int mt = 0; mt < 2; mt++)
                #pragma unroll
                for (int nt = 0; nt < 8; nt++)
                    mma16816(acc[mt][nt], aa[mt], bb[nt >> 1][(nt & 1) * 2], bb[nt >> 1][(nt & 1) * 2 + 1]);
        }

        // refill stage (it+2)%3 == (it-1)%3; its readers were fenced by the
        // barrier at the top of THIS iteration, so no second barrier needed.
        if (it + 2 < NIT) {
            fill_stage(sb + (uint32_t)((it + 2) % 3) * STAGE_BYTES, it + 2, tid, m0, n0g);
            CP_COMMIT();
        }
    }

    __syncthreads();   // all compute done before smem reuse

    // ---- epilogue: accums -> SMEM (row stride 132 f32) ----
    float* epi = reinterpret_cast<float*>(sm);
    #pragma unroll
    for (int mt = 0; mt < 2; mt++) {
        #pragma unroll
        for (int nt = 0; nt < 8; nt++) {
            const int m = wm + mt * 16 + (lane >> 2);
            const int n = wn + nt * 8 + (lane & 3) * 2;
            *reinterpret_cast<float2*>(&epi[m * EPI_LD + n]) =
                make_float2(acc[mt][nt][0], acc[mt][nt][1]);
            *reinterpret_cast<float2*>(&epi[(m + 8) * EPI_LD + n]) =
                make_float2(acc[mt][nt][2], acc[mt][nt][3]);
        }
    }

    // ---- prefetch c_old into registers ACROSS the barrier ----
    const int h_loc = tid & 31;       // 32 h per CTA
    const int mrow0 = tid >> 5;       // 8 row groups
    float cold[16];
    #pragma unroll
    for (int j = 0; j < 16; j++)
        cold[j] = c_old[(size_t)(m0 + mrow0 + 8 * j) * 512 + h0 + h_loc];

    __syncthreads();

    // ---- gates + state update ----
    {
        const size_t BH = (size_t)B * 512;
        const float bi = bU[0 * 512 + h0 + h_loc] + bW[0 * 512 + h0 + h_loc];
        const float bf = bU[1 * 512 + h0 + h_loc] + bW[1 * 512 + h0 + h_loc];
        const float bo = bU[2 * 512 + h0 + h_loc] + bW[2 * 512 + h0 + h_loc];
        const float bc = bU[3 * 512 + h0 + h_loc] + bW[3 * 512 + h0 + h_loc];

        #pragma unroll
        for (int j = 0; j < 16; j++) {
            const int m = mrow0 + 8 * j;
            float4 gv = *reinterpret_cast<const float4*>(&epi[m * EPI_LD + h_loc * 4]);
            const float i_t = sigmoidf_(gv.x + bi);
            const float f_t = sigmoidf_(gv.y + bf);
            const float o_t = sigmoidf_(gv.z + bo);
            const float c_t = tanhf_(gv.w + bc);
            const size_t off = (size_t)(m0 + m) * 512 + h0 + h_loc;
            const float cn = i_t * c_t + f_t * cold[j];
            out[off]      = o_t * tanhf_(cn);   // h_new
            out[BH + off] = cn;                 // c_new
        }
    }
}

// ---------------------------------------------------------------------------
extern "C" void kernel_launch(void* const* d_in, const int* in_sizes, int n_in,
                              void* d_out, int out_size)
{
    const float* x     = (const float*)d_in[0];  // [B, 256]
    const float* h_old = (const float*)d_in[1];  // [B, 512]
    const float* c_old = (const float*)d_in[2];  // [B, 512]
    const float* U     = (const float*)d_in[3];  // [4, 256, 512]
    const float* bU    = (const float*)d_in[4];  // [4, 512]
    const float* W     = (const float*)d_in[5];  // [4, 512, 512]
    const float* bW    = (const float*)d_in[6];  // [4, 512]
    float* out = (float*)d_out;                  // [2, B, 512]

    int B = in_sizes[0] / 256;

    cudaFuncSetAttribute(lstm_mma_kernel,
                         cudaFuncAttributeMaxDynamicSharedMemorySize, SM_TOTAL);

    int ptasks = B * 192 + WTASKS;
    lstm_prep<<<(ptasks + 255) / 256, 256>>>(x, h_old, U, W, B);

    dim3 grid(2048 / BN, B / BM);   // (16, 512) — n fastest for L2 A-stripe reuse
    lstm_mma_kernel<<<grid, NTHR, SM_TOTAL>>>(c_old, bU, bW, out, B);
}